// round 14
// baseline (speedup 1.0000x reference)
#include <cuda_runtime.h>
#include <cuda_fp16.h>
#include <stdint.h>

#define DIM_I 128
#define DIM_G 16
#define DIM_O 128
#define NCHUNKS 32               // chunk = 4 input dims = 128 k-steps
#define SUBP 16384               // sub-plane: 128 rows x 64 fp16 (128B rows)
#define A_BYTES 32768            // 2 A sub-planes
#define B_BYTES 32768            // 2 B sub-planes
#define ST_BYTES (A_BYTES + B_BYTES)         // 65536
#define NSTAGES 3
#define SM_PAR  (NSTAGES * ST_BYTES)         // 196608 ; bias|gamma|beta
#define SMEM_TOTAL (SM_PAR + 3 * 128 * 4)    // 198144
#define EPI_STRIDE 132

// Pre-converted fp16 weights, pre-swizzled, 16KB per 64-k sub-chunk
__device__ __align__(16) unsigned char g_B[64 * SUBP];   // 1 MB

__device__ __forceinline__ uint32_t smem_u32(const void* p) {
    uint32_t a;
    asm("{ .reg .u64 t; cvta.to.shared.u64 t, %1; cvt.u32.u64 %0, t; }" : "=r"(a) : "l"(p));
    return a;
}
__device__ __forceinline__ void ldsm4(uint32_t& r0, uint32_t& r1, uint32_t& r2,
                                      uint32_t& r3, uint32_t a) {
    asm volatile("ldmatrix.sync.aligned.m8n8.x4.shared.b16 {%0,%1,%2,%3}, [%4];"
                 : "=r"(r0), "=r"(r1), "=r"(r2), "=r"(r3) : "r"(a));
}
// f16-accumulate MMA, C = 0: one k16 dot per output, promoted outside.
__device__ __forceinline__ void mma16816_f16(uint32_t& d0, uint32_t& d1,
                                             const uint32_t* a, const uint32_t* b) {
    asm volatile(
        "mma.sync.aligned.m16n8k16.row.col.f16.f16.f16.f16 "
        "{%0,%1}, {%2,%3,%4,%5}, {%6,%7}, {%8,%9};"
        : "=r"(d0), "=r"(d1)
        : "r"(a[0]), "r"(a[1]), "r"(a[2]), "r"(a[3]),
          "r"(b[0]), "r"(b[1]), "r"(0u), "r"(0u));
}
#define CP_ASYNC16(dst, src) \
    asm volatile("cp.async.cg.shared.global [%0], [%1], 16;" :: "r"(dst), "l"(src) : "memory")
#define CP_COMMIT()    asm volatile("cp.async.commit_group;" ::: "memory")
#define CP_WAIT(n)     asm volatile("cp.async.wait_group %0;" :: "n"(n) : "memory")
// named barriers: full[s]=1..3, empty[s]=4..6, consumer epi=7
#define BAR_SYNC(id, cnt)   asm volatile("bar.sync %0, %1;"   :: "r"(id), "r"(cnt) : "memory")
#define BAR_ARRIVE(id, cnt) asm volatile("bar.arrive %0, %1;" :: "r"(id), "r"(cnt) : "memory")

// ---------------------------------------------------------------------------
// Prep v2: thread = (o, i). 8x LDG.128 + 4x STG.128 into swizzled layout.
// sub-chunk = i>>1 ; k_local = (i&1)*32 + 2g + {0=cos,1=sin}.
// ---------------------------------------------------------------------------
__global__ void prep_weights(const float* __restrict__ cosA,
                             const float* __restrict__ sinA) {
    int t = blockIdx.x * blockDim.x + threadIdx.x;   // over O*I = 16384
    if (t >= DIM_O * DIM_I) return;
    const int o = t >> 7, i = t & 127;
    const float* cp = cosA + (size_t)t * DIM_G;
    const float* sp = sinA + (size_t)t * DIM_G;
    float4 c4[4], s4[4];
    #pragma unroll
    for (int j = 0; j < 4; ++j) {
        c4[j] = ((const float4*)cp)[j];
        s4[j] = ((const float4*)sp)[j];
    }
    const int sc = i >> 1;
    const int kl0c = (i & 1) * 32 >> 3;              // base 16B-chunk index
    unsigned char* dst = g_B + (size_t)sc * SUBP + o * 128;
    #pragma unroll
    for (int j = 0; j < 4; ++j) {
        const float* cc = (const float*)&c4[j];
        const float* ss = (const float*)&s4[j];
        uint4 wv;
        half2 h0 = __floats2half2_rn(cc[0], ss[0]);
        half2 h1 = __floats2half2_rn(cc[1], ss[1]);
        half2 h2 = __floats2half2_rn(cc[2], ss[2]);
        half2 h3 = __floats2half2_rn(cc[3], ss[3]);
        wv.x = *(uint32_t*)&h0; wv.y = *(uint32_t*)&h1;
        wv.z = *(uint32_t*)&h2; wv.w = *(uint32_t*)&h3;
        *(uint4*)(dst + (((kl0c + j) ^ (o & 7)) << 4)) = wv;
    }
}

// ---------------------------------------------------------------------------
// Main: BM=128, 1 CTA/SM, warp-specialized, 3-stage ring of 128-k chunks.
// Warps 0-3 = producers (trig A + cp.async B). Warps 4-7 = consumers
// (64m x 64n, f16-acc MMA promoted per-MMA to f32). Fused bias + LN.
// ---------------------------------------------------------------------------
__global__ __launch_bounds__(256, 1)
void fkan_ws(const float* __restrict__ X,
             const float* __restrict__ bias,
             const float* __restrict__ gamma,
             const float* __restrict__ beta,
             float* __restrict__ Out) {
    extern __shared__ unsigned char smem[];
    const uint32_t sb = smem_u32(smem);
    const int tid = threadIdx.x, w = tid >> 5, lane = tid & 31;
    const int n0blk = blockIdx.x * 128;

    if (tid >= 128) {
        ((float*)(smem + SM_PAR))[tid - 128]       = bias[tid - 128];
        ((float*)(smem + SM_PAR))[tid]             = gamma[tid - 128];
        ((float*)(smem + SM_PAR))[tid + 128]       = beta[tid - 128];
    }

    if (tid < 128) {
        // ================= PRODUCER (threads 0..127; thread = row) =========
        const int p = tid;                           // row 0..127
        uint32_t aoff[8];                            // [(dim&1)*4 + q]
        #pragma unroll
        for (int j = 0; j < 8; ++j)
            aoff[j] = (uint32_t)(p * 128 + ((j ^ (p & 7)) << 4));
        const float* xrow = X + (size_t)(n0blk + p) * DIM_I;

        float4 xq = *(const float4*)xrow;            // dims 0..3 (chunk 0)
        for (int pc = 0; pc < NCHUNKS; ++pc) {
            const int s = pc % NSTAGES;
            unsigned char* stgp = smem + s * ST_BYTES;
            const uint32_t stg = sb + (uint32_t)(s * ST_BYTES);
            if (pc >= NSTAGES) BAR_SYNC(4 + s, 256);         // wait empty[s]
            float4 xn;
            if (pc + 1 < NCHUNKS)
                xn = *(const float4*)(xrow + 4 * (pc + 1));  // prefetch X
            // ---- gen A: 4 dims for this row -> 2 sub-planes ----
            const float xv4[4] = {xq.x, xq.y, xq.z, xq.w};
            #pragma unroll
            for (int hd = 0; hd < 4; ++hd) {
                float xv = xv4[hd];
                float s1, c1;
                __sincosf(xv, &s1, &c1);
                uint32_t hv[16];
                float cg = c1, sg = s1;
                #pragma unroll
                for (int g = 0; g < 16; ++g) {
                    if (g) {
                        float cn = fmaf(cg, c1, -(sg * s1));
                        float sn = fmaf(sg, c1,  (cg * s1));
                        cg = cn; sg = sn;
                    }
                    half2 h = __floats2half2_rn(cg, sg);
                    hv[g] = *(uint32_t*)&h;
                }
                unsigned char* apl = stgp + (hd >> 1) * SUBP;
                const int j0 = (hd & 1) * 4;
                #pragma unroll
                for (int q = 0; q < 4; ++q)
                    *(uint4*)(apl + aoff[j0 + q]) =
                        make_uint4(hv[4*q], hv[4*q+1], hv[4*q+2], hv[4*q+3]);
            }
            // ---- cp.async B: 32KB (sub-chunks 2pc, 2pc+1) ----
            const unsigned char* gsrc = g_B + (size_t)pc * B_BYTES;
            #pragma unroll
            for (int j = 0; j < 16; ++j) {
                uint32_t idx = (uint32_t)(p + j * 128) * 16u;
                CP_ASYNC16(stg + A_BYTES + idx, gsrc + idx);
            }
            CP_COMMIT();
            // deferred publish of chunk pc-1 (its cp group + smem stores done)
            if (pc >= 1) {
                CP_WAIT(1);
                BAR_ARRIVE(1 + ((pc - 1) % NSTAGES), 256);
            }
            xq = xn;
        }
        CP_WAIT(0);
        BAR_ARRIVE(1 + ((NCHUNKS - 1) % NSTAGES), 256);      // full[last]
        return;
    }

    // ====== CONSUMER (threads 128..255, warps 4-7, 64m x 64n) ======
    const int wc = w - 4;                            // 0..3
    const int mi = wc & 1, ni = wc >> 1;
    const int r8 = lane & 7, bsel = lane >> 3;
    const int kbA = bsel >> 1;
    const int mr0 = mi * 64 + r8 + ((bsel & 1) << 3);
    uint32_t moA[4];
    #pragma unroll
    for (int mt = 0; mt < 4; ++mt) moA[mt] = (uint32_t)((mr0 + 16 * mt) * 128);
    const int kbB = bsel & 1;
    const int nrb = ni * 64 + r8 + ((bsel >> 1) << 3);
    uint32_t noB[4];
    #pragma unroll
    for (int t = 0; t < 4; ++t) noB[t] = (uint32_t)((nrb + 16 * t) * 128);
    uint32_t kxA[4], kxB[4];
    #pragma unroll
    for (int ks = 0; ks < 4; ++ks) {
        kxA[ks] = (uint32_t)((((ks << 1) | kbA) ^ (mr0 & 7)) << 4);
        kxB[ks] = (uint32_t)((((ks << 1) | kbB) ^ (nrb & 7)) << 4);
    }

    float acc[4][8][4];
    #pragma unroll
    for (int mt = 0; mt < 4; ++mt)
        #pragma unroll
        for (int nt = 0; nt < 8; ++nt)
            #pragma unroll
            for (int j = 0; j < 4; ++j) acc[mt][nt][j] = 0.f;

    for (int c = 0; c < NCHUNKS; ++c) {
        const int s = c % NSTAGES;
        const uint32_t stg = sb + (uint32_t)(s * ST_BYTES);
        BAR_SYNC(1 + s, 256);                        // wait full[s]
        #pragma unroll
        for (int sp = 0; sp < 2; ++sp) {
            const uint32_t AH = stg + (uint32_t)(sp * SUBP);
            const uint32_t BP = stg + A_BYTES + (uint32_t)(sp * SUBP);
            #pragma unroll
            for (int ks = 0; ks < 4; ++ks) {
                uint32_t af[4][4], bf[16];
                #pragma unroll
                for (int mt = 0; mt < 4; ++mt)
                    ldsm4(af[mt][0], af[mt][1], af[mt][2], af[mt][3],
                          AH + moA[mt] + kxA[ks]);
                #pragma unroll
                for (int t = 0; t < 4; ++t)
                    ldsm4(bf[4*t], bf[4*t+1], bf[4*t+2], bf[4*t+3],
                          BP + noB[t] + kxB[ks]);
                #pragma unroll
                for (int mt = 0; mt < 4; ++mt)
                    #pragma unroll
                    for (int nt = 0; nt < 8; ++nt) {
                        const uint32_t* b = &bf[(nt >> 1) * 4 + (nt & 1) * 2];
                        uint32_t d0, d1;
                        mma16816_f16(d0, d1, af[mt], b);
                        float2 f0 = __half22float2(*(__half2*)&d0);
                        float2 f1 = __half22float2(*(__half2*)&d1);
                        acc[mt][nt][0] += f0.x;
                        acc[mt][nt][1] += f0.y;
                        acc[mt][nt][2] += f1.x;
                        acc[mt][nt][3] += f1.y;
                    }
            }
        }
        BAR_ARRIVE(4 + s, 256);                      // empty[s]
    }

    // ---- epilogue: acc -> f32 smem tile ----
    {
        float* tile = (float*)smem;                  // 128 x 132 f32 = 67.6KB
        const int g4 = lane >> 2, t4 = lane & 3;
        #pragma unroll
        for (int mt = 0; mt < 4; ++mt)
            #pragma unroll
            for (int nt = 0; nt < 8; ++nt) {
                int rowm = mi * 64 + mt * 16 + g4;
                int col  = ni * 64 + nt * 8 + 2 * t4;
                *(float2*)&tile[rowm * EPI_STRIDE + col] =
                    make_float2(acc[mt][nt][0], acc[mt][nt][1]);
                *(float2*)&tile[(rowm + 8) * EPI_STRIDE + col] =
                    make_float2(acc[mt][nt][2], acc[mt][nt][3]);
            }
    }
    BAR_SYNC(7, 128);                                // consumers only

    // ---- two-pass LN: thread = row ----
    {
        const int r = tid - 128;                     // 0..127
        const float* tile = (const float*)smem;
        const float* bS  = (const float*)(smem + SM_PAR);
        const float* gS  = bS + 128;
        const float* btS = bS + 256;
        float s = 0.f, q = 0.f;
        #pragma unroll
        for (int j4 = 0; j4 < 32; ++j4) {
            float4 t4v = *(const float4*)&tile[r * EPI_STRIDE + j4 * 4];
            float a0 = t4v.x + bS[j4*4+0], a1 = t4v.y + bS[j4*4+1];
            float a2 = t4v.z + bS[j4*4+2], a3 = t4v.w + bS[j4*4+3];
            s += (a0 + a1) + (a2 + a3);
            q += a0*a0 + a1*a1 + a2*a2 + a3*a3;
        }
        float mu  = s * (1.0f / 128.0f);
        float var = q * (1.0f / 128.0f) - mu * mu;
        float rs  = rsqrtf(var + 1e-5f);
        float4* op = (float4*)(Out + (size_t)(n0blk + r) * DIM_O);
        #pragma unroll
        for (int j4 = 0; j4 < 32; ++j4) {
            float4 t4v = *(const float4*)&tile[r * EPI_STRIDE + j4 * 4];
            float4 o;
            o.x = (t4v.x + bS[j4*4+0] - mu) * rs * gS[j4*4+0] + btS[j4*4+0];
            o.y = (t4v.y + bS[j4*4+1] - mu) * rs * gS[j4*4+1] + btS[j4*4+1];
            o.z = (t4v.z + bS[j4*4+2] - mu) * rs * gS[j4*4+2] + btS[j4*4+2];
            o.w = (t4v.w + bS[j4*4+3] - mu) * rs * gS[j4*4+3] + btS[j4*4+3];
            op[j4] = o;
        }
    }
}

// ---------------------------------------------------------------------------
extern "C" void kernel_launch(void* const* d_in, const int* in_sizes, int n_in,
                              void* d_out, int out_size) {
    const float* x     = (const float*)d_in[0];
    const float* cosA  = (const float*)d_in[1];
    const float* sinA  = (const float*)d_in[2];
    const float* bias  = (const float*)d_in[3];
    const float* gamma = (const float*)d_in[4];
    const float* beta  = (const float*)d_in[5];
    float* out = (float*)d_out;

    const int N = in_sizes[0] / DIM_I;

    cudaFuncSetAttribute(fkan_ws, cudaFuncAttributeMaxDynamicSharedMemorySize,
                         SMEM_TOTAL);

    prep_weights<<<(DIM_O * DIM_I + 255) / 256, 256>>>(cosA, sinA);
    fkan_ws<<<N / 128, 256, SMEM_TOTAL>>>(x, bias, gamma, beta, out);
}

// round 15
// speedup vs baseline: 1.2809x; 1.2809x over previous
#include <cuda_runtime.h>
#include <cuda_fp16.h>
#include <stdint.h>

#define DIM_I 128
#define DIM_G 16
#define DIM_O 128
#define NCHUNKS 32               // chunk = 4 input dims = 128 k-steps
#define SUBP 16384               // sub-plane: 128 rows x 64 fp16 (128B rows)
#define A_BYTES 32768            // 2 A sub-planes
#define B_BYTES 32768            // 2 B sub-planes
#define ST_BYTES (A_BYTES + B_BYTES)         // 65536
#define NSTAGES 3
#define SM_PAR  (NSTAGES * ST_BYTES)         // 196608 ; bias|gamma|beta
#define SMEM_TOTAL (SM_PAR + 3 * 128 * 4)    // 198144
#define EPI_STRIDE 132

__device__ __forceinline__ uint32_t smem_u32(const void* p) {
    uint32_t a;
    asm("{ .reg .u64 t; cvta.to.shared.u64 t, %1; cvt.u32.u64 %0, t; }" : "=r"(a) : "l"(p));
    return a;
}
__device__ __forceinline__ void ldsm4(uint32_t& r0, uint32_t& r1, uint32_t& r2,
                                      uint32_t& r3, uint32_t a) {
    asm volatile("ldmatrix.sync.aligned.m8n8.x4.shared.b16 {%0,%1,%2,%3}, [%4];"
                 : "=r"(r0), "=r"(r1), "=r"(r2), "=r"(r3) : "r"(a));
}
__device__ __forceinline__ void mma16816(float* d, const uint32_t* a, const uint32_t* b) {
    asm volatile(
        "mma.sync.aligned.m16n8k16.row.col.f32.f16.f16.f32 "
        "{%0,%1,%2,%3}, {%4,%5,%6,%7}, {%8,%9}, {%0,%1,%2,%3};"
        : "+f"(d[0]), "+f"(d[1]), "+f"(d[2]), "+f"(d[3])
        : "r"(a[0]), "r"(a[1]), "r"(a[2]), "r"(a[3]), "r"(b[0]), "r"(b[1]));
}
// named barriers: full[s]=1..3, empty[s]=4..6, consumer epi=7
#define BAR_SYNC(id, cnt)   asm volatile("bar.sync %0, %1;"   :: "r"(id), "r"(cnt) : "memory")
#define BAR_ARRIVE(id, cnt) asm volatile("bar.arrive %0, %1;" :: "r"(id), "r"(cnt) : "memory")

// ---------------------------------------------------------------------------
// Single fused kernel: BM=128, 1 CTA/SM, warp-specialized, 3-stage ring of
// 128-k chunks. Warps 0-3 = producers: trig-recurrence A features AND on-the-
// fly fp32->fp16 conversion of weights (B) from gmem (L2-resident) into the
// swizzled smem tiles. Warps 4-7 = consumers: 64m x 64n f32-acc mma.sync.
// Fused bias + LayerNorm epilogue. No prep kernel, no global scratch.
// ---------------------------------------------------------------------------
__global__ __launch_bounds__(256, 1)
void fkan_ws(const float* __restrict__ X,
             const float* __restrict__ cosA,
             const float* __restrict__ sinA,
             const float* __restrict__ bias,
             const float* __restrict__ gamma,
             const float* __restrict__ beta,
             float* __restrict__ Out) {
    extern __shared__ unsigned char smem[];
    const uint32_t sb = smem_u32(smem);
    const int tid = threadIdx.x, w = tid >> 5, lane = tid & 31;
    const int n0blk = blockIdx.x * 128;

    if (tid >= 128) {
        ((float*)(smem + SM_PAR))[tid - 128] = bias[tid - 128];
        ((float*)(smem + SM_PAR))[tid]       = gamma[tid - 128];
        ((float*)(smem + SM_PAR))[tid + 128] = beta[tid - 128];
    }

    if (tid < 128) {
        // ========== PRODUCER (threads 0..127; thread = row = o) ============
        const int p = tid;
        uint32_t aoff[8];                            // [(dim&1)*4 + q], swizzled
        #pragma unroll
        for (int j = 0; j < 8; ++j)
            aoff[j] = (uint32_t)(p * 128 + ((j ^ (p & 7)) << 4));
        const float* xrow = X + (size_t)(n0blk + p) * DIM_I;
        const float* crow = cosA + (size_t)p * (DIM_I * DIM_G);
        const float* srow = sinA + (size_t)p * (DIM_I * DIM_G);

        float4 xq = *(const float4*)xrow;            // dims 0..3 (chunk 0)
        for (int pc = 0; pc < NCHUNKS; ++pc) {
            const int s = pc % NSTAGES;
            unsigned char* stgp = smem + s * ST_BYTES;
            if (pc >= NSTAGES) BAR_SYNC(4 + s, 256);         // wait empty[s]
            float4 xn;
            if (pc + 1 < NCHUNKS)
                xn = *(const float4*)(xrow + 4 * (pc + 1));  // prefetch X
            const float xv4[4] = {xq.x, xq.y, xq.z, xq.w};

            #pragma unroll
            for (int h = 0; h < 2; ++h) {            // sub-plane = 2 dims
                // ---- issue B fp32 loads first (L2 latency hides under trig)
                float4 cb[2][4], sv[2][4];
                #pragma unroll
                for (int d = 0; d < 2; ++d) {
                    const int dim = 4 * pc + 2 * h + d;
                    const float4* cp = (const float4*)(crow + dim * DIM_G);
                    const float4* sp = (const float4*)(srow + dim * DIM_G);
                    #pragma unroll
                    for (int q = 0; q < 4; ++q) {
                        cb[d][q] = cp[q];
                        sv[d][q] = sp[q];
                    }
                }
                // ---- gen A: trig recurrence for the 2 dims ----
                #pragma unroll
                for (int d = 0; d < 2; ++d) {
                    float xv = xv4[2 * h + d];
                    float s1, c1;
                    __sincosf(xv, &s1, &c1);
                    uint32_t hv[16];
                    float cg = c1, sg = s1;
                    #pragma unroll
                    for (int g = 0; g < 16; ++g) {
                        if (g) {
                            float cn = fmaf(cg, c1, -(sg * s1));
                            float sn = fmaf(sg, c1,  (cg * s1));
                            cg = cn; sg = sn;
                        }
                        half2 hh = __floats2half2_rn(cg, sg);
                        hv[g] = *(uint32_t*)&hh;
                    }
                    unsigned char* apl = stgp + h * SUBP;
                    #pragma unroll
                    for (int q = 0; q < 4; ++q)
                        *(uint4*)(apl + aoff[d * 4 + q]) =
                            make_uint4(hv[4*q], hv[4*q+1], hv[4*q+2], hv[4*q+3]);
                }
                // ---- convert + store B fp16 ----
                unsigned char* bpl = stgp + A_BYTES + h * SUBP;
                #pragma unroll
                for (int d = 0; d < 2; ++d) {
                    #pragma unroll
                    for (int q = 0; q < 4; ++q) {
                        const float* cc = (const float*)&cb[d][q];
                        const float* ss = (const float*)&sv[d][q];
                        half2 h0 = __floats2half2_rn(cc[0], ss[0]);
                        half2 h1 = __floats2half2_rn(cc[1], ss[1]);
                        half2 h2 = __floats2half2_rn(cc[2], ss[2]);
                        half2 h3 = __floats2half2_rn(cc[3], ss[3]);
                        uint4 wv;
                        wv.x = *(uint32_t*)&h0; wv.y = *(uint32_t*)&h1;
                        wv.z = *(uint32_t*)&h2; wv.w = *(uint32_t*)&h3;
                        *(uint4*)(bpl + aoff[d * 4 + q]) = wv;
                    }
                }
            }
            BAR_ARRIVE(1 + s, 256);                  // publish full[s]
            xq = xn;
        }
        return;
    }

    // ====== CONSUMER (threads 128..255, warps 4-7, 64m x 64n, f32-acc) =====
    const int wc = w - 4;                            // 0..3
    const int mi = wc & 1, ni = wc >> 1;
    const int r8 = lane & 7, bsel = lane >> 3;
    const int kbA = bsel >> 1;
    const int mr0 = mi * 64 + r8 + ((bsel & 1) << 3);
    uint32_t moA[4];
    #pragma unroll
    for (int mt = 0; mt < 4; ++mt) moA[mt] = (uint32_t)((mr0 + 16 * mt) * 128);
    const int kbB = bsel & 1;
    const int nrb = ni * 64 + r8 + ((bsel >> 1) << 3);
    uint32_t noB[4];
    #pragma unroll
    for (int t = 0; t < 4; ++t) noB[t] = (uint32_t)((nrb + 16 * t) * 128);
    uint32_t kxA[4], kxB[4];
    #pragma unroll
    for (int ks = 0; ks < 4; ++ks) {
        kxA[ks] = (uint32_t)((((ks << 1) | kbA) ^ (mr0 & 7)) << 4);
        kxB[ks] = (uint32_t)((((ks << 1) | kbB) ^ (nrb & 7)) << 4);
    }

    float acc[4][8][4];
    #pragma unroll
    for (int mt = 0; mt < 4; ++mt)
        #pragma unroll
        for (int nt = 0; nt < 8; ++nt)
            #pragma unroll
            for (int j = 0; j < 4; ++j) acc[mt][nt][j] = 0.f;

    for (int c = 0; c < NCHUNKS; ++c) {
        const int s = c % NSTAGES;
        const uint32_t stg = sb + (uint32_t)(s * ST_BYTES);
        BAR_SYNC(1 + s, 256);                        // wait full[s]
        #pragma unroll
        for (int sp = 0; sp < 2; ++sp) {
            const uint32_t AH = stg + (uint32_t)(sp * SUBP);
            const uint32_t BP = stg + A_BYTES + (uint32_t)(sp * SUBP);
            #pragma unroll
            for (int ks = 0; ks < 4; ++ks) {
                uint32_t af[4][4], bf[16];
                #pragma unroll
                for (int mt = 0; mt < 4; ++mt)
                    ldsm4(af[mt][0], af[mt][1], af[mt][2], af[mt][3],
                          AH + moA[mt] + kxA[ks]);
                #pragma unroll
                for (int t = 0; t < 4; ++t)
                    ldsm4(bf[4*t], bf[4*t+1], bf[4*t+2], bf[4*t+3],
                          BP + noB[t] + kxB[ks]);
                #pragma unroll
                for (int mt = 0; mt < 4; ++mt)
                    #pragma unroll
                    for (int nt = 0; nt < 8; ++nt) {
                        const uint32_t* b = &bf[(nt >> 1) * 4 + (nt & 1) * 2];
                        mma16816(acc[mt][nt], af[mt], b);
                    }
            }
        }
        BAR_ARRIVE(4 + s, 256);                      // empty[s]
    }

    // ---- epilogue: acc -> f32 smem tile ----
    {
        float* tile = (float*)smem;                  // 128 x 132 f32 = 67.6KB
        const int g4 = lane >> 2, t4 = lane & 3;
        #pragma unroll
        for (int mt = 0; mt < 4; ++mt)
            #pragma unroll
            for (int nt = 0; nt < 8; ++nt) {
                int rowm = mi * 64 + mt * 16 + g4;
                int col  = ni * 64 + nt * 8 + 2 * t4;
                *(float2*)&tile[rowm * EPI_STRIDE + col] =
                    make_float2(acc[mt][nt][0], acc[mt][nt][1]);
                *(float2*)&tile[(rowm + 8) * EPI_STRIDE + col] =
                    make_float2(acc[mt][nt][2], acc[mt][nt][3]);
            }
    }
    BAR_SYNC(7, 128);                                // consumers only

    // ---- two-pass LN: thread = row ----
    {
        const int r = tid - 128;                     // 0..127
        const float* tile = (const float*)smem;
        const float* bS  = (const float*)(smem + SM_PAR);
        const float* gS  = bS + 128;
        const float* btS = bS + 256;
        float s = 0.f, q = 0.f;
        #pragma unroll
        for (int j4 = 0; j4 < 32; ++j4) {
            float4 t4v = *(const float4*)&tile[r * EPI_STRIDE + j4 * 4];
            float a0 = t4v.x + bS[j4*4+0], a1 = t4v.y + bS[j4*4+1];
            float a2 = t4v.z + bS[j4*4+2], a3 = t4v.w + bS[j4*4+3];
            s += (a0 + a1) + (a2 + a3);
            q += a0*a0 + a1*a1 + a2*a2 + a3*a3;
        }
        float mu  = s * (1.0f / 128.0f);
        float var = q * (1.0f / 128.0f) - mu * mu;
        float rs  = rsqrtf(var + 1e-5f);
        float4* op = (float4*)(Out + (size_t)(n0blk + r) * DIM_O);
        #pragma unroll
        for (int j4 = 0; j4 < 32; ++j4) {
            float4 t4v = *(const float4*)&tile[r * EPI_STRIDE + j4 * 4];
            float4 o;
            o.x = (t4v.x + bS[j4*4+0] - mu) * rs * gS[j4*4+0] + btS[j4*4+0];
            o.y = (t4v.y + bS[j4*4+1] - mu) * rs * gS[j4*4+1] + btS[j4*4+1];
            o.z = (t4v.z + bS[j4*4+2] - mu) * rs * gS[j4*4+2] + btS[j4*4+2];
            o.w = (t4v.w + bS[j4*4+3] - mu) * rs * gS[j4*4+3] + btS[j4*4+3];
            op[j4] = o;
        }
    }
}

// ---------------------------------------------------------------------------
extern "C" void kernel_launch(void* const* d_in, const int* in_sizes, int n_in,
                              void* d_out, int out_size) {
    const float* x     = (const float*)d_in[0];
    const float* cosA  = (const float*)d_in[1];
    const float* sinA  = (const float*)d_in[2];
    const float* bias  = (const float*)d_in[3];
    const float* gamma = (const float*)d_in[4];
    const float* beta  = (const float*)d_in[5];
    float* out = (float*)d_out;

    const int N = in_sizes[0] / DIM_I;

    cudaFuncSetAttribute(fkan_ws, cudaFuncAttributeMaxDynamicSharedMemorySize,
                         SMEM_TOTAL);

    fkan_ws<<<N / 128, 256, SMEM_TOTAL>>>(x, cosA, sinA, bias, gamma, beta, out);
}

// round 16
// speedup vs baseline: 2.5583x; 1.9972x over previous
#include <cuda_runtime.h>
#include <cuda_fp16.h>
#include <stdint.h>

#define DIM_I 128
#define DIM_G 16
#define DIM_O 128
#define NCHUNKS 64               // chunk = 2 input dims = 64 k-steps
#define A_BYTES 16384            // 128 rows x 64 fp16
#define B_BYTES 16384            // 128 o-rows x 64 fp16
#define ST_BYTES (A_BYTES + B_BYTES)         // 32768
#define NSTAGES 4
#define SM_PAR  (NSTAGES * ST_BYTES)         // 131072 ; bias|gamma|beta
#define SMEM_TOTAL (SM_PAR + 3 * 128 * 4)    // 132608
#define EPI_STRIDE 132

// Pre-converted fp16 weights, pre-swizzled, 16KB per 64-k chunk
__device__ __align__(16) unsigned char g_B[NCHUNKS * B_BYTES];   // 1 MB

__device__ __forceinline__ uint32_t smem_u32(const void* p) {
    uint32_t a;
    asm("{ .reg .u64 t; cvta.to.shared.u64 t, %1; cvt.u32.u64 %0, t; }" : "=r"(a) : "l"(p));
    return a;
}
__device__ __forceinline__ void ldsm4(uint32_t& r0, uint32_t& r1, uint32_t& r2,
                                      uint32_t& r3, uint32_t a) {
    asm volatile("ldmatrix.sync.aligned.m8n8.x4.shared.b16 {%0,%1,%2,%3}, [%4];"
                 : "=r"(r0), "=r"(r1), "=r"(r2), "=r"(r3) : "r"(a));
}
__device__ __forceinline__ void mma16816(float* d, const uint32_t* a, const uint32_t* b) {
    asm volatile(
        "mma.sync.aligned.m16n8k16.row.col.f32.f16.f16.f32 "
        "{%0,%1,%2,%3}, {%4,%5,%6,%7}, {%8,%9}, {%0,%1,%2,%3};"
        : "+f"(d[0]), "+f"(d[1]), "+f"(d[2]), "+f"(d[3])
        : "r"(a[0]), "r"(a[1]), "r"(a[2]), "r"(a[3]), "r"(b[0]), "r"(b[1]));
}
#define CP_ASYNC16(dst, src) \
    asm volatile("cp.async.cg.shared.global [%0], [%1], 16;" :: "r"(dst), "l"(src) : "memory")
#define CP_COMMIT()    asm volatile("cp.async.commit_group;" ::: "memory")
#define CP_WAIT(n)     asm volatile("cp.async.wait_group %0;" :: "n"(n) : "memory")
// named barriers: full[s]=1+s (1..4), empty[s]=5+s (5..8), consumer epi=9
#define BAR_SYNC(id, cnt)   asm volatile("bar.sync %0, %1;"   :: "r"(id), "r"(cnt) : "memory")
#define BAR_ARRIVE(id, cnt) asm volatile("bar.arrive %0, %1;" :: "r"(id), "r"(cnt) : "memory")

// ---------------------------------------------------------------------------
// Prep: weights -> fp16, {cos,sin} adjacent in k, swizzled 128B rows.
// chunk = i>>1 ; k_local = (i&1)*32 + 2g + {0=cos,1=sin}.
// ---------------------------------------------------------------------------
__global__ void prep_weights(const float* __restrict__ cosA,
                             const float* __restrict__ sinA) {
    int t = blockIdx.x * blockDim.x + threadIdx.x;   // over O*I*G = 262144
    if (t >= DIM_O * DIM_I * DIM_G) return;
    int o = t >> 11, rem = t & 2047, i = rem >> 4, g = rem & 15;
    half2 w = __floats2half2_rn(cosA[t], sinA[t]);   // lo=cos, hi=sin
    int sc = i >> 1;
    int kl = (i & 1) * 32 + 2 * g;
    int cidx = kl >> 3;
    uint32_t off = (uint32_t)(o * 128 + ((cidx ^ (o & 7)) << 4) + (kl & 7) * 2);
    *(uint32_t*)(g_B + (size_t)sc * B_BYTES + off) = *(uint32_t*)&w;
}

// ---------------------------------------------------------------------------
// Main: BM=128, 1 CTA/SM, warp-specialized. Threads 0-127 = consumers
// (4 warps, 64m x 64n, ldsm double-buffered across ks). Threads 128-255 =
// producers (trig A + cp.async B). 4-stage ring, deferred arrive. Fused LN.
// ---------------------------------------------------------------------------
__global__ __launch_bounds__(256, 1)
void fkan_ws(const float* __restrict__ X,
             const float* __restrict__ bias,
             const float* __restrict__ gamma,
             const float* __restrict__ beta,
             float* __restrict__ Out) {
    extern __shared__ unsigned char smem[];
    const uint32_t sb = smem_u32(smem);
    const int tid = threadIdx.x, w = tid >> 5, lane = tid & 31;
    const int n0blk = blockIdx.x * 128;

    if (tid < 128) {
        ((float*)(smem + SM_PAR))[tid]       = bias[tid];
        ((float*)(smem + SM_PAR))[128 + tid] = gamma[tid];
        ((float*)(smem + SM_PAR))[256 + tid] = beta[tid];
    }

    if (tid >= 128) {
        // ================= PRODUCER (threads 128..255; thread = row) =======
        const int p = tid - 128;                     // row 0..127
        uint32_t aoff[8];                            // [hd*4 + q]
        #pragma unroll
        for (int j = 0; j < 8; ++j)
            aoff[j] = (uint32_t)(p * 128 + ((j ^ (p & 7)) << 4));
        const float* xrow = X + (size_t)(n0blk + p) * DIM_I;

        float2 xq = *(const float2*)xrow;            // dims 0,1 (chunk 0)
        for (int pc = 0; pc < NCHUNKS; ++pc) {
            const int s = pc & 3;
            unsigned char* stgp = smem + s * ST_BYTES;
            const uint32_t stg = sb + (uint32_t)(s * ST_BYTES);
            if (pc >= NSTAGES) BAR_SYNC(5 + s, 256);         // wait empty[s]
            float2 xn;
            if (pc + 1 < NCHUNKS)
                xn = *(const float2*)(xrow + 2 * (pc + 1));  // prefetch X
            // ---- gen A: 2 dims for this row (k 0..31 and 32..63) ----
            #pragma unroll
            for (int hd = 0; hd < 2; ++hd) {
                float xv = hd ? xq.y : xq.x;
                float s1, c1;
                __sincosf(xv, &s1, &c1);
                uint32_t hv[16];
                float cg = c1, sg = s1;
                #pragma unroll
                for (int g = 0; g < 16; ++g) {
                    if (g) {
                        float cn = fmaf(cg, c1, -(sg * s1));
                        float sn = fmaf(sg, c1,  (cg * s1));
                        cg = cn; sg = sn;
                    }
                    half2 h = __floats2half2_rn(cg, sg);
                    hv[g] = *(uint32_t*)&h;
                }
                #pragma unroll
                for (int q = 0; q < 4; ++q)
                    *(uint4*)(stgp + aoff[hd * 4 + q]) =
                        make_uint4(hv[4*q], hv[4*q+1], hv[4*q+2], hv[4*q+3]);
            }
            // ---- cp.async B: 16KB for this chunk ----
            const unsigned char* gsrc = g_B + (size_t)pc * B_BYTES;
            #pragma unroll
            for (int j = 0; j < 8; ++j) {
                uint32_t idx = (uint32_t)(p + j * 128) * 16u;
                CP_ASYNC16(stg + A_BYTES + idx, gsrc + idx);
            }
            CP_COMMIT();
            // deferred publish of chunk pc-1 (its cp group + smem stores done)
            if (pc >= 1) {
                CP_WAIT(1);
                BAR_ARRIVE(1 + ((pc - 1) & 3), 256);
            }
            xq = xn;
        }
        CP_WAIT(0);
        BAR_ARRIVE(1 + ((NCHUNKS - 1) & 3), 256);            // full[last]
        return;
    }

    // ================= CONSUMER (threads 0..127, 4 warps, 64m x 64n) =======
    const int mi = w & 1, ni = w >> 1;
    const int r8 = lane & 7, bsel = lane >> 3;
    const int kbA = bsel >> 1;
    const int mr0 = mi * 64 + r8 + ((bsel & 1) << 3);
    uint32_t moA[4];
    #pragma unroll
    for (int mt = 0; mt < 4; ++mt) moA[mt] = (uint32_t)((mr0 + 16 * mt) * 128);
    const int kbB = bsel & 1;
    const int nrb = ni * 64 + r8 + ((bsel >> 1) << 3);
    uint32_t noB[4];
    #pragma unroll
    for (int t = 0; t < 4; ++t) noB[t] = (uint32_t)((nrb + 16 * t) * 128);
    uint32_t kxA[4], kxB[4];
    #pragma unroll
    for (int ks = 0; ks < 4; ++ks) {
        kxA[ks] = (uint32_t)((((ks << 1) | kbA) ^ (mr0 & 7)) << 4);
        kxB[ks] = (uint32_t)((((ks << 1) | kbB) ^ (nrb & 7)) << 4);
    }

    float acc[4][8][4];
    #pragma unroll
    for (int mt = 0; mt < 4; ++mt)
        #pragma unroll
        for (int nt = 0; nt < 8; ++nt)
            #pragma unroll
            for (int j = 0; j < 4; ++j) acc[mt][nt][j] = 0.f;

    for (int c = 0; c < NCHUNKS; ++c) {
        const int s = c & 3;
        const uint32_t stg = sb + (uint32_t)(s * ST_BYTES);
        const uint32_t AH = stg, BP = stg + A_BYTES;
        BAR_SYNC(1 + s, 256);                        // wait full[s]
        uint32_t af[2][4][4], bf[2][16];
        // prime ks=0 operands
        #pragma unroll
        for (int mt = 0; mt < 4; ++mt)
            ldsm4(af[0][mt][0], af[0][mt][1], af[0][mt][2], af[0][mt][3],
                  AH + moA[mt] + kxA[0]);
        #pragma unroll
        for (int t = 0; t < 4; ++t)
            ldsm4(bf[0][4*t], bf[0][4*t+1], bf[0][4*t+2], bf[0][4*t+3],
                  BP + noB[t] + kxB[0]);
        #pragma unroll
        for (int ks = 0; ks < 4; ++ks) {
            const int cur = ks & 1, nxt = cur ^ 1;
            if (ks < 3) {                            // prefetch ks+1 operands
                #pragma unroll
                for (int mt = 0; mt < 4; ++mt)
                    ldsm4(af[nxt][mt][0], af[nxt][mt][1],
                          af[nxt][mt][2], af[nxt][mt][3],
                          AH + moA[mt] + kxA[ks + 1]);
                #pragma unroll
                for (int t = 0; t < 4; ++t)
                    ldsm4(bf[nxt][4*t], bf[nxt][4*t+1],
                          bf[nxt][4*t+2], bf[nxt][4*t+3],
                          BP + noB[t] + kxB[ks + 1]);
            }
            #pragma unroll
            for (int mt = 0; mt < 4; ++mt)
                #pragma unroll
                for (int nt = 0; nt < 8; ++nt) {
                    const uint32_t* b = &bf[cur][(nt >> 1) * 4 + (nt & 1) * 2];
                    mma16816(acc[mt][nt], af[cur][mt], b);
                }
        }
        BAR_ARRIVE(5 + s, 256);                      // empty[s]
    }

    // ---- epilogue: acc -> f32 smem tile ----
    {
        float* tile = (float*)smem;                  // 128 x 132 f32 = 67.6KB
        const int g4 = lane >> 2, t4 = lane & 3;
        #pragma unroll
        for (int mt = 0; mt < 4; ++mt)
            #pragma unroll
            for (int nt = 0; nt < 8; ++nt) {
                int rowm = mi * 64 + mt * 16 + g4;
                int col  = ni * 64 + nt * 8 + 2 * t4;
                *(float2*)&tile[rowm * EPI_STRIDE + col] =
                    make_float2(acc[mt][nt][0], acc[mt][nt][1]);
                *(float2*)&tile[(rowm + 8) * EPI_STRIDE + col] =
                    make_float2(acc[mt][nt][2], acc[mt][nt][3]);
            }
    }
    BAR_SYNC(9, 128);                                // consumers only

    // ---- two-pass LN (no big register array): thread = row ----
    {
        const int r = tid;                           // 0..127
        const float* tile = (const float*)smem;
        const float* bS  = (const float*)(smem + SM_PAR);
        const float* gS  = bS + 128;
        const float* btS = bS + 256;
        float s = 0.f, q = 0.f;
        #pragma unroll
        for (int j4 = 0; j4 < 32; ++j4) {
            float4 t4v = *(const float4*)&tile[r * EPI_STRIDE + j4 * 4];
            float a0 = t4v.x + bS[j4*4+0], a1 = t4v.y + bS[j4*4+1];
            float a2 = t4v.z + bS[j4*4+2], a3 = t4v.w + bS[j4*4+3];
            s += (a0 + a1) + (a2 + a3);
            q += a0*a0 + a1*a1 + a2*a2 + a3*a3;
        }
        float mu  = s * (1.0f / 128.0f);
        float var = q * (1.0f / 128.0f) - mu * mu;
        float rs  = rsqrtf(var + 1e-5f);
        float4* op = (float4*)(Out + (size_t)(n0blk + r) * DIM_O);
        #pragma unroll
        for (int j4 = 0; j4 < 32; ++j4) {
            float4 t4v = *(const float4*)&tile[r * EPI_STRIDE + j4 * 4];
            float4 o;
            o.x = (t4v.x + bS[j4*4+0] - mu) * rs * gS[j4*4+0] + btS[j4*4+0];
            o.y = (t4v.y + bS[j4*4+1] - mu) * rs * gS[j4*4+1] + btS[j4*4+1];
            o.z = (t4v.z + bS[j4*4+2] - mu) * rs * gS[j4*4+2] + btS[j4*4+2];
            o.w = (t4v.w + bS[j4*4+3] - mu) * rs * gS[j4*4+3] + btS[j4*4+3];
            op[j4] = o;
        }
    }
}

// ---------------------------------------------------------------------------
extern "C" void kernel_launch(void* const* d_in, const int* in_sizes, int n_in,
                              void* d_out, int out_size) {
    const float* x     = (const float*)d_in[0];
    const float* cosA  = (const float*)d_in[1];
    const float* sinA  = (const float*)d_in[2];
    const float* bias  = (const float*)d_in[3];
    const float* gamma = (const float*)d_in[4];
    const float* beta  = (const float*)d_in[5];
    float* out = (float*)d_out;

    const int N = in_sizes[0] / DIM_I;

    cudaFuncSetAttribute(fkan_ws, cudaFuncAttributeMaxDynamicSharedMemorySize,
                         SMEM_TOTAL);

    const int tw = DIM_O * DIM_I * DIM_G;
    prep_weights<<<(tw + 255) / 256, 256>>>(cosA, sinA);
    fkan_ws<<<N / 128, 256, SMEM_TOTAL>>>(x, bias, gamma, beta, out);
}